// round 4
// baseline (speedup 1.0000x reference)
#include <cuda_runtime.h>
#include <math.h>
#include <stdint.h>

#define N_NODES 100000
#define E_EDGES 400000
#define HID 128
#define HD 256

// ---------------- scratch (static device globals; no allocation) ----------------
__device__ float    g_h[(size_t)N_NODES * HID];
__device__ float    g_q[(size_t)N_NODES * HD];
__device__ float    g_k[(size_t)N_NODES * HD];
__device__ float    g_v[(size_t)N_NODES * HD];
__device__ float    g_out[(size_t)N_NODES * HD];   // skip, then += attention agg
__device__ unsigned g_smax[(size_t)N_NODES * 4];   // ordered-uint encoded float max
__device__ float    g_denom[(size_t)N_NODES * 4];
__device__ float    g_e[(size_t)E_EDGES * 4];      // scores, then exp(scores - max)

// monotone float <-> uint mapping for atomicMax on floats
__device__ __forceinline__ unsigned fenc(float f) {
    unsigned b = __float_as_uint(f);
    return (b & 0x80000000u) ? ~b : (b | 0x80000000u);
}
__device__ __forceinline__ float fdec(unsigned u) {
    unsigned b = (u & 0x80000000u) ? (u & 0x7fffffffu) : ~u;
    return __uint_as_float(b);
}

// ---------------- kernels ----------------

__global__ void init_kernel() {
    int i = blockIdx.x * blockDim.x + threadIdx.x;
    if (i < N_NODES * 4) { g_smax[i] = 0u; g_denom[i] = 0.f; }
}

__global__ void addh_kernel(const float4* __restrict__ x, const float4* __restrict__ mem) {
    int i = blockIdx.x * blockDim.x + threadIdx.x;
    if (i < N_NODES * HID / 4) {
        float4 a = x[i], b = mem[i];
        float4 c = make_float4(a.x + b.x, a.y + b.y, a.z + b.z, a.w + b.w);
        ((float4*)g_h)[i] = c;
    }
}

// C[sel] = g_h[M,128] @ W[128,256] + b ; sel: 0=q 1=k 2=v 3=out(skip)
__global__ void gemm_bias_kernel(const float* __restrict__ W, const float* __restrict__ b, int sel) {
    __shared__ float sA[64][68];  // [k][row]
    __shared__ float sB[64][64];  // [k][col]
    float* C = (sel == 0) ? g_q : (sel == 1) ? g_k : (sel == 2) ? g_v : g_out;

    int row0 = blockIdx.x * 64;
    int col0 = blockIdx.y * 64;
    int tid = threadIdx.x;
    int tx = tid & 15, ty = tid >> 4;
    float acc[4][4] = {};

    for (int kt = 0; kt < 2; ++kt) {
        int k0 = kt * 64;
#pragma unroll
        for (int i = 0; i < 16; i++) {
            int idx = tid + i * 256;           // 64 rows x 64 k
            int r = idx >> 6, kk = idx & 63;
            int gr = row0 + r;
            float v = (gr < N_NODES) ? g_h[(size_t)gr * HID + k0 + kk] : 0.f;
            sA[kk][r] = v;
        }
#pragma unroll
        for (int i = 0; i < 16; i++) {
            int idx = tid + i * 256;           // 64 k x 64 cols
            int kk = idx >> 6, c = idx & 63;
            sB[kk][c] = W[(size_t)(k0 + kk) * HD + col0 + c];
        }
        __syncthreads();
#pragma unroll
        for (int kk = 0; kk < 64; ++kk) {
            float a[4], bb[4];
#pragma unroll
            for (int i = 0; i < 4; i++) a[i] = sA[kk][ty * 4 + i];
#pragma unroll
            for (int j = 0; j < 4; j++) bb[j] = sB[kk][tx * 4 + j];
#pragma unroll
            for (int i = 0; i < 4; i++)
#pragma unroll
                for (int j = 0; j < 4; j++) acc[i][j] = fmaf(a[i], bb[j], acc[i][j]);
        }
        __syncthreads();
    }
#pragma unroll
    for (int i = 0; i < 4; i++) {
        int gr = row0 + ty * 4 + i;
        if (gr < N_NODES) {
#pragma unroll
            for (int j = 0; j < 4; j++) {
                int gc = col0 + tx * 4 + j;
                C[(size_t)gr * HD + gc] = acc[i][j] + b[gc];
            }
        }
    }
}

// one warp per edge: scores[e][h] = dot64(q[dst],k[src]) / 8 ; atomicMax into g_smax
__global__ void scores_kernel(const int* __restrict__ ei) {
    int w = (blockIdx.x * blockDim.x + threadIdx.x) >> 5;
    int lane = threadIdx.x & 31;
    if (w >= E_EDGES) return;
    int src = ei[w];
    int dst = ei[E_EDGES + w];
    const float* qd = g_q + (size_t)dst * HD;
    const float* ks = g_k + (size_t)src * HD;
#pragma unroll
    for (int h = 0; h < 4; ++h) {
        float p = qd[h * 64 + lane] * ks[h * 64 + lane]
                + qd[h * 64 + 32 + lane] * ks[h * 64 + 32 + lane];
#pragma unroll
        for (int o = 16; o > 0; o >>= 1) p += __shfl_xor_sync(0xffffffffu, p, o);
        p *= 0.125f;
        if (lane == 0) {
            g_e[(size_t)w * 4 + h] = p;
            atomicMax(&g_smax[(size_t)dst * 4 + h], fenc(p));
        }
    }
}

__global__ void expden_kernel(const int* __restrict__ ei) {
    int i = blockIdx.x * blockDim.x + threadIdx.x;
    if (i >= E_EDGES * 4) return;
    int e = i >> 2, h = i & 3;
    int dst = ei[E_EDGES + e];
    float m = fdec(g_smax[(size_t)dst * 4 + h]);
    float ex = expf(g_e[i] - m);
    g_e[i] = ex;
    atomicAdd(&g_denom[(size_t)dst * 4 + h], ex);
}

// one warp per edge: out[dst] += alpha * v[src]
__global__ void agg_kernel(const int* __restrict__ ei) {
    int w = (blockIdx.x * blockDim.x + threadIdx.x) >> 5;
    int lane = threadIdx.x & 31;
    if (w >= E_EDGES) return;
    int src = ei[w];
    int dst = ei[E_EDGES + w];
    const float* vs = g_v + (size_t)src * HD;
    float* od = g_out + (size_t)dst * HD;
#pragma unroll
    for (int h = 0; h < 4; ++h) {
        float alpha = g_e[(size_t)w * 4 + h] / (g_denom[(size_t)dst * 4 + h] + 1e-16f);
        atomicAdd(&od[h * 64 + lane], alpha * vs[h * 64 + lane]);
        atomicAdd(&od[h * 64 + 32 + lane], alpha * vs[h * 64 + 32 + lane]);
    }
}

// fused edge MLP: per block 64 edges
// inter[512] = [out[src] | out[dst]] ; h1 = relu(inter@W1+b1) [128]
// h2 = relu(h1@W2+b2) [64] ; rating = sigmoid(h2@W3+b3)*4+1
__global__ void edge_mlp_kernel(const int* __restrict__ ei,
                                const float* __restrict__ W1, const float* __restrict__ b1,
                                const float* __restrict__ W2, const float* __restrict__ b2,
                                const float* __restrict__ W3, const float* __restrict__ b3,
                                float* __restrict__ out) {
    extern __shared__ float smem[];
    __shared__ int s_src[64], s_dst[64];

    int e0 = blockIdx.x * 64;
    int tid = threadIdx.x;
    if (tid < 64) {
        s_src[tid] = ei[e0 + tid];
        s_dst[tid] = ei[E_EDGES + e0 + tid];
    }
    __syncthreads();

    int tx = tid & 15, ty = tid >> 4;

    // ---------- layer 1: [64 edges x 128] accum, K=512 in chunks of 64 ----------
    float acc[4][8] = {};
    float* sAT = smem;             // [64 k][68 edges]
    float* sW1 = smem + 64 * 68;   // [64 k][128 c]
    for (int kt = 0; kt < 8; ++kt) {
        int k0 = kt * 64;
#pragma unroll
        for (int i = 0; i < 16; i++) {
            int idx = tid + i * 256;          // 64 edges x 64 k
            int e = idx >> 6, kk = idx & 63;
            int col = k0 + kk;
            float v;
            if (col < HD) v = g_out[(size_t)s_src[e] * HD + col];
            else          v = g_out[(size_t)s_dst[e] * HD + (col - HD)];
            sAT[kk * 68 + e] = v;
        }
#pragma unroll
        for (int i = 0; i < 32; i++) {
            int idx = tid + i * 256;          // 64 k x 128 c
            int kk = idx >> 7, c = idx & 127;
            sW1[kk * 128 + c] = W1[(size_t)(k0 + kk) * 128 + c];
        }
        __syncthreads();
#pragma unroll
        for (int kk = 0; kk < 64; ++kk) {
            float a[4], bb[8];
#pragma unroll
            for (int i = 0; i < 4; i++) a[i] = sAT[kk * 68 + ty * 4 + i];
#pragma unroll
            for (int j = 0; j < 8; j++) bb[j] = sW1[kk * 128 + tx * 8 + j];
#pragma unroll
            for (int i = 0; i < 4; i++)
#pragma unroll
                for (int j = 0; j < 8; j++) acc[i][j] = fmaf(a[i], bb[j], acc[i][j]);
        }
        __syncthreads();
    }

    // ---------- layer 2: relu(h1) in smem, then [64 x 64], K=128 ----------
    float* sH1 = smem;             // [64 edges][132]
    float* sW2 = smem + 64 * 132;  // [128][64]
#pragma unroll
    for (int i = 0; i < 4; i++) {
        int e = ty * 4 + i;
#pragma unroll
        for (int j = 0; j < 8; j++) {
            int c = tx * 8 + j;
            sH1[e * 132 + c] = fmaxf(acc[i][j] + b1[c], 0.f);
        }
    }
#pragma unroll
    for (int i = 0; i < 32; i++) {
        int idx = tid + i * 256;              // 128x64
        sW2[idx] = W2[idx];
    }
    __syncthreads();

    float acc2[4][4] = {};
#pragma unroll
    for (int kk = 0; kk < 128; ++kk) {
        float a[4], bb[4];
#pragma unroll
        for (int i = 0; i < 4; i++) a[i] = sH1[(ty * 4 + i) * 132 + kk];
#pragma unroll
        for (int j = 0; j < 4; j++) bb[j] = sW2[kk * 64 + tx * 4 + j];
#pragma unroll
        for (int i = 0; i < 4; i++)
#pragma unroll
            for (int j = 0; j < 4; j++) acc2[i][j] = fmaf(a[i], bb[j], acc2[i][j]);
    }
    __syncthreads();

    // ---------- layer 3: relu(h2) -> dot with W3 -> sigmoid*4+1 ----------
    float* sH2 = smem;             // [64 edges][68]
    float* sW3 = smem + 64 * 68;   // [64]
#pragma unroll
    for (int i = 0; i < 4; i++) {
        int e = ty * 4 + i;
#pragma unroll
        for (int j = 0; j < 4; j++) {
            int c = tx * 4 + j;
            sH2[e * 68 + c] = fmaxf(acc2[i][j] + b2[c], 0.f);
        }
    }
    if (tid < 64) sW3[tid] = W3[tid];
    __syncthreads();

    if (tid < 64) {
        float z = b3[0];
#pragma unroll
        for (int kk = 0; kk < 64; ++kk) z = fmaf(sH2[tid * 68 + kk], sW3[kk], z);
        float r = 4.f / (1.f + expf(-z)) + 1.f;
        out[e0 + tid] = r;
    }
}

// ---------------- host launcher ----------------
extern "C" void kernel_launch(void* const* d_in, const int* in_sizes, int n_in,
                              void* d_out, int out_size) {
    const int* ei = (const int*)d_in[0];   // int64 in reference -> int32 via harness
    // d_in[1] = edge_time (unused by forward)
    const float* x   = (const float*)d_in[2];
    const float* mem = (const float*)d_in[3];
    const float* Wq = (const float*)d_in[4];  const float* bq = (const float*)d_in[5];
    const float* Wk = (const float*)d_in[6];  const float* bk = (const float*)d_in[7];
    const float* Wv = (const float*)d_in[8];  const float* bv = (const float*)d_in[9];
    const float* Ws = (const float*)d_in[10]; const float* bs = (const float*)d_in[11];
    const float* W1 = (const float*)d_in[12]; const float* b1 = (const float*)d_in[13];
    const float* W2 = (const float*)d_in[14]; const float* b2 = (const float*)d_in[15];
    const float* W3 = (const float*)d_in[16]; const float* b3 = (const float*)d_in[17];
    float* out = (float*)d_out;

    // 64*132 + 128*64 floats = 66560 B of dynamic smem for the fused MLP
    cudaFuncSetAttribute(edge_mlp_kernel, cudaFuncAttributeMaxDynamicSharedMemorySize, 66560);

    init_kernel<<<(N_NODES * 4 + 255) / 256, 256>>>();
    addh_kernel<<<(N_NODES * HID / 4 + 255) / 256, 256>>>((const float4*)x, (const float4*)mem);

    dim3 gg((N_NODES + 63) / 64, HD / 64);
    gemm_bias_kernel<<<gg, 256>>>(Wq, bq, 0);
    gemm_bias_kernel<<<gg, 256>>>(Wk, bk, 1);
    gemm_bias_kernel<<<gg, 256>>>(Wv, bv, 2);
    gemm_bias_kernel<<<gg, 256>>>(Ws, bs, 3);   // skip connection -> g_out

    scores_kernel<<<(E_EDGES * 32 + 255) / 256, 256>>>(ei);
    expden_kernel<<<(E_EDGES * 4 + 255) / 256, 256>>>(ei);
    agg_kernel<<<(E_EDGES * 32 + 255) / 256, 256>>>(ei);

    edge_mlp_kernel<<<E_EDGES / 64, 256, 66560>>>(ei, W1, b1, W2, b2, W3, b3, out);
}